// round 8
// baseline (speedup 1.0000x reference)
#include <cuda_runtime.h>

// FDTD wave update:
//   u2 = 2*u1 - u0 + (DT^2 * C^2 / DX^2) * lap5(u1) - (DT/(2*EPS)) * (j2 - j0)
// DX=0.01, DT=0.005, C=1, EPS=1  =>  lap coeff = 0.25, current coeff = 0.0025
// Zero ("same") padding: out-of-bounds neighbors are 0.
//
// Shapes: (16, 1, 1024, 1024) fp32. Pure HBM-bound stencil.

#define IMG_W 1024
#define IMG_H 1024
#define IMG_B 16

__global__ __launch_bounds__(256)
void fdtd_step_kernel(const float* __restrict__ u1,
                      const float* __restrict__ u0,
                      const float* __restrict__ j2,
                      const float* __restrict__ j0,
                      float* __restrict__ out)
{
    const int t   = threadIdx.x;      // 0..255, each handles 4 contiguous x
    const int row = blockIdx.x;       // 0..1023
    const int img = blockIdx.y;       // 0..15

    const long base = (long)img * (IMG_H * IMG_W) + (long)row * IMG_W;
    const int  x0   = t << 2;         // 0,4,...,1020 (16B aligned)

    // Center row of u1 (always in-bounds)
    const float4 c = *reinterpret_cast<const float4*>(u1 + base + x0);

    // Vertical neighbors (zero at top/bottom boundary)
    float4 up = make_float4(0.f, 0.f, 0.f, 0.f);
    float4 dn = make_float4(0.f, 0.f, 0.f, 0.f);
    if (row > 0)
        up = *reinterpret_cast<const float4*>(u1 + base - IMG_W + x0);
    if (row < IMG_H - 1)
        dn = *reinterpret_cast<const float4*>(u1 + base + IMG_W + x0);

    // Horizontal halo scalars (zero at left/right boundary).
    // These hit L1/L2 — the same row was just streamed by neighboring threads.
    const float left  = (t > 0)   ? __ldg(u1 + base + x0 - 1) : 0.f;
    const float right = (t < 255) ? __ldg(u1 + base + x0 + 4) : 0.f;

    // Remaining elementwise inputs
    const float4 a = *reinterpret_cast<const float4*>(u0 + base + x0);
    const float4 p = *reinterpret_cast<const float4*>(j2 + base + x0);
    const float4 q = *reinterpret_cast<const float4*>(j0 + base + x0);

    // Folded constants: DT^2*C^2/DX^2 = 0.25 ; DT/(2*EPS) = 0.0025
    const float KL = 0.25f;
    const float KJ = 0.0025f;

    float4 r;
    r.x = 2.f * c.x - a.x
        + KL * (up.x + dn.x + left + c.y - 4.f * c.x)
        - KJ * (p.x - q.x);
    r.y = 2.f * c.y - a.y
        + KL * (up.y + dn.y + c.x + c.z - 4.f * c.y)
        - KJ * (p.y - q.y);
    r.z = 2.f * c.z - a.z
        + KL * (up.z + dn.z + c.y + c.w - 4.f * c.z)
        - KJ * (p.z - q.z);
    r.w = 2.f * c.w - a.w
        + KL * (up.w + dn.w + c.z + right - 4.f * c.w)
        - KJ * (p.w - q.w);

    *reinterpret_cast<float4*>(out + base + x0) = r;
}

extern "C" void kernel_launch(void* const* d_in, const int* in_sizes, int n_in,
                              void* d_out, int out_size)
{
    const float* u1 = (const float*)d_in[0];
    const float* u0 = (const float*)d_in[1];
    const float* j2 = (const float*)d_in[2];
    const float* j0 = (const float*)d_in[3];
    float* out = (float*)d_out;

    dim3 grid(IMG_H, IMG_B);
    dim3 block(256);
    fdtd_step_kernel<<<grid, block>>>(u1, u0, j2, j0, out);
}